// round 16
// baseline (speedup 1.0000x reference)
#include <cuda_runtime.h>
#include <math.h>

#define NV 2
#define NB 16384
#define NC 100
#define ND 512
#define CHUNKS 2
#define MAIN_BLOCKS (NV * NC * CHUNKS)            // 400
#define BUILD_BLOCKS 16
#define MARGIN_F 10.0f

// Scratch (no dynamic allocation allowed)
__device__ int   g_rowidx[NC * NB];               // per-class compacted row lists
__device__ int   g_ccount[NC];                    // per-class counts (zero-init; reset by tail)
__device__ float g_partials[MAIN_BLOCKS];         // per-block diff^2 partial sums
__device__ float g_inter[NV];                     // per-v inter_loss
__device__ unsigned int g_count = 0;              // completion counter (reset by tail)

__device__ __forceinline__ void red_count_one() {
    asm volatile("red.release.gpu.global.add.u32 [%0], 1;"
                 :: "l"(&g_count) : "memory");
}

// ---- kernel 1: build lists (16 blocks) + anchor stats (2 blocks) ----
__global__ void __launch_bounds__(1024) build_and_stats(
    const int* __restrict__ label,
    const float* __restrict__ anchor)
{
    const int tid = threadIdx.x;

    if (blockIdx.x < BUILD_BLOCKS) {
        __shared__ int cnt[NC];
        __shared__ int base[NC];
        if (tid < NC) cnt[tid] = 0;
        __syncthreads();

        const int i = blockIdx.x * 1024 + tid;    // 16 * 1024 = 16384
        int l = min(max(__ldg(&label[i]), 0), NC - 1);
        int slot = atomicAdd(&cnt[l], 1);         // SMEM: spread-address, fast
        __syncthreads();

        if (tid < NC) base[tid] = atomicAdd(&g_ccount[tid], cnt[tid]);  // depth 16
        __syncthreads();

        g_rowidx[l * NB + base[l] + slot] = i;
    } else {
        // anchor stats, one block per v. 512 active threads (d index).
        // pair_sum = C * sum_c ||a_c||^2 - ||sum_c a_c||^2 (pd diagonal is 0)
        const int v = blockIdx.x - BUILD_BLOCKS;
        __shared__ float shs[512], shq[512];
        if (tid < 512) {
            const float* a = anchor + (size_t)v * NC * ND;
            float m = 0.f, s = 0.f;
            #pragma unroll 4
            for (int c = 0; c < NC; c++) {
                float x = a[(size_t)c * ND + tid];
                m += x;
                s = fmaf(x, x, s);
            }
            shs[tid] = s; shq[tid] = m * m;
        }
        __syncthreads();
        #pragma unroll
        for (int off = 256; off > 0; off >>= 1) {
            if (tid < off) { shs[tid] += shs[tid + off]; shq[tid] += shq[tid + off]; }
            __syncthreads();
        }
        if (tid == 0) {
            float S  = shs[0];
            float M2 = shq[0];
            float inter = (NC * S - M2) / (float)(NC * (NC - 1));
            g_inter[v] = fmaxf(MARGIN_F - inter, 0.0f);
        }
    }
}

// ---- kernel 2: main (400 blocks) with fused tail on block 0 ----
__global__ void __launch_bounds__(512) anchor_loss_main(
    const float* __restrict__ feat,
    const float* __restrict__ anchor,
    float* __restrict__ out)                      // out[0]=loss, out[1..]=sims
{
    const int tid  = threadIdx.x;
    const int warp = tid >> 5;
    const int lane = tid & 31;

    const int v     = blockIdx.x / (NC * CHUNKS);
    const int rem   = blockIdx.x % (NC * CHUNKS);
    const int c     = rem / CHUNKS;
    const int chunk = rem % CHUNKS;

    __shared__ float4 sc[ND / 4];                 // 2 KB center row
    __shared__ float  s_cn;
    __shared__ float  s_wsum[16];

    // stage center row (128 float4 by first 128 threads)
    const float4* c4 = reinterpret_cast<const float4*>(anchor)
                       + ((size_t)v * NC + c) * (ND / 4);
    if (tid < 128) sc[tid] = c4[tid];
    __syncthreads();

    // warp 0 computes ||c||^2 once
    if (warp == 0) {
        float cn = 0.f;
        #pragma unroll
        for (int k = 0; k < 4; k++) {
            float4 x = sc[lane + 32 * k];
            cn = fmaf(x.x, x.x, fmaf(x.y, x.y, fmaf(x.z, x.z, fmaf(x.w, x.w, cn))));
        }
        #pragma unroll
        for (int off = 16; off > 0; off >>= 1)
            cn += __shfl_xor_sync(0xffffffffu, cn, off);
        if (lane == 0) s_cn = cn;
    }
    __syncthreads();
    const float cn    = s_cn;
    const float cnorm = fmaxf(sqrtf(cn), 1e-8f);
    const int   n     = g_ccount[c];

    float dsum = 0.f;                             // accumulated on lane 0 only
    int j = chunk * 16 + warp;                    // 32 warp-slots stride the list
    int row = (j < n) ? g_rowidx[c * NB + j] : 0;
    for (; j < n; j += 32) {
        int nrow = (j + 32 < n) ? g_rowidx[c * NB + j + 32] : 0;  // prefetch
        const float4* f4 = reinterpret_cast<const float4*>(feat)
                           + ((size_t)v * NB + row) * (ND / 4);
        float dt = 0.f, fn = 0.f;
        #pragma unroll
        for (int k = 0; k < 4; k++) {
            float4 f = f4[lane + 32 * k];
            float4 cc = sc[lane + 32 * k];
            dt = fmaf(f.x, cc.x, fmaf(f.y, cc.y, fmaf(f.z, cc.z, fmaf(f.w, cc.w, dt))));
            fn = fmaf(f.x, f.x, fmaf(f.y, f.y, fmaf(f.z, f.z, fmaf(f.w, f.w, fn))));
        }
        #pragma unroll
        for (int off = 16; off > 0; off >>= 1) {
            dt += __shfl_xor_sync(0xffffffffu, dt, off);
            fn += __shfl_xor_sync(0xffffffffu, fn, off);
        }
        if (lane == 0) {
            out[1 + v * NB + row] = dt / (fmaxf(sqrtf(fn), 1e-8f) * cnorm);
            dsum += fn - 2.f * dt + cn;           // ||f-c||^2
        }
        row = nrow;
    }

    if (lane == 0) s_wsum[warp] = dsum;
    __syncthreads();
    if (tid == 0) {
        float t = 0.f;
        #pragma unroll
        for (int w = 0; w < 16; w++) t += s_wsum[w];
        g_partials[blockIdx.x] = t;
        red_count_one();                          // fire-and-forget publish
    }

    if (blockIdx.x != 0) return;

    // ---- block 0 is the finalizer: poll, then deterministic reduce ----
    if (tid == 0) {
        unsigned int cdone;
        do {
            asm volatile("ld.acquire.gpu.global.u32 %0, [%1];"
                         : "=r"(cdone) : "l"(&g_count));
            if (cdone < MAIN_BLOCKS) __nanosleep(64);
        } while (cdone < MAIN_BLOCKS);
    }
    __syncthreads();

    __shared__ float s0[512];
    {
        float p = (tid < MAIN_BLOCKS) ? __ldcg(&g_partials[tid]) : 0.f;
        s0[tid] = p;
    }
    __syncthreads();
    #pragma unroll
    for (int off = 256; off > 0; off >>= 1) {
        if (tid < off) s0[tid] += s0[tid + off];
        __syncthreads();
    }
    if (tid == 0) {
        float center_mean = s0[0] / (2.0f * (float)NV * (float)NB);
        float inter_mean  = (g_inter[0] + g_inter[1]) / (float)NV;
        out[0] = center_mean + inter_mean;
        g_count = 0;                              // reset for next graph replay
    }
    if (tid < NC) g_ccount[tid] = 0;              // reset class counters too
}

extern "C" void kernel_launch(void* const* d_in, const int* in_sizes, int n_in,
                              void* d_out, int out_size)
{
    const float* feat   = (const float*)d_in[0];
    const int*   label  = (const int*)d_in[1];
    const float* anchor = (const float*)d_in[2];
    float* out = (float*)d_out;

    build_and_stats<<<BUILD_BLOCKS + NV, 1024>>>(label, anchor);
    anchor_loss_main<<<MAIN_BLOCKS, 512>>>(feat, anchor, out);
}

// round 17
// speedup vs baseline: 1.1218x; 1.1218x over previous
#include <cuda_runtime.h>
#include <math.h>

#define NV 2
#define NB 16384
#define NC 100
#define ND 512
#define ROWS_PER_WARP 2
#define ROWS_PER_BLOCK 16                        // 8 warps * 2 rows
#define BLOCKS_PER_V (NB / ROWS_PER_BLOCK)       // 1024
#define MAIN_BLOCKS (NV * BLOCKS_PER_V)          // 2048
#define MARGIN_F 10.0f

// Scratch (no dynamic allocation allowed)
__device__ float g_partials[MAIN_BLOCKS];        // per-block diff^2 partial sums
__device__ float g_inter[NV];                    // per-v inter_loss

__global__ void __launch_bounds__(256) anchor_loss_main(
    const float* __restrict__ feat,
    const int* __restrict__ label,               // int32 (JAX x64 disabled)
    const float* __restrict__ anchor,
    float* __restrict__ out)                     // out[0]=loss, out[1..]=sims
{
    if (blockIdx.x < MAIN_BLOCKS) {
        // ---- main pass: 2 rows per warp; feat loads front-batched (MLP=8) ----
        const int warp = threadIdx.x >> 5;
        const int lane = threadIdx.x & 31;
        const int r0   = blockIdx.x * ROWS_PER_BLOCK + warp * ROWS_PER_WARP;
        const int r1   = r0 + 1;
        const int v    = r0 >> 14;
        const int b0   = r0 & (NB - 1);
        const int b1   = r1 & (NB - 1);

        const float4* f4a = reinterpret_cast<const float4*>(feat) + (size_t)r0 * (ND / 4);
        const float4* f4b = reinterpret_cast<const float4*>(feat) + (size_t)r1 * (ND / 4);

        // Front-batch ALL 8 feat loads (DRAM latency) before anything else.
        float4 fa0 = f4a[lane +  0], fa1 = f4a[lane + 32],
               fa2 = f4a[lane + 64], fa3 = f4a[lane + 96];
        float4 fb0 = f4b[lane +  0], fb1 = f4b[lane + 32],
               fb2 = f4b[lane + 64], fb3 = f4b[lane + 96];

        int l0 = min(max(__ldg(&label[b0]), 0), NC - 1);
        int l1 = min(max(__ldg(&label[b1]), 0), NC - 1);
        const float4* c4a = reinterpret_cast<const float4*>(anchor)
                            + ((size_t)v * NC + l0) * (ND / 4);
        const float4* c4b = reinterpret_cast<const float4*>(anchor)
                            + ((size_t)v * NC + l1) * (ND / 4);

        float dt0 = 0.f, fn0 = 0.f, cn0 = 0.f;
        float dt1 = 0.f, fn1 = 0.f, cn1 = 0.f;

        // Center loads (L2/L1-resident) interleave with compute.
        #pragma unroll
        for (int k = 0; k < 4; k++) {
            float4 f0 = (k == 0) ? fa0 : (k == 1) ? fa1 : (k == 2) ? fa2 : fa3;
            float4 f1 = (k == 0) ? fb0 : (k == 1) ? fb1 : (k == 2) ? fb2 : fb3;
            float4 c0 = c4a[lane + 32 * k];
            float4 c1 = c4b[lane + 32 * k];
            dt0 = fmaf(f0.x, c0.x, fmaf(f0.y, c0.y, fmaf(f0.z, c0.z, fmaf(f0.w, c0.w, dt0))));
            fn0 = fmaf(f0.x, f0.x, fmaf(f0.y, f0.y, fmaf(f0.z, f0.z, fmaf(f0.w, f0.w, fn0))));
            cn0 = fmaf(c0.x, c0.x, fmaf(c0.y, c0.y, fmaf(c0.z, c0.z, fmaf(c0.w, c0.w, cn0))));
            dt1 = fmaf(f1.x, c1.x, fmaf(f1.y, c1.y, fmaf(f1.z, c1.z, fmaf(f1.w, c1.w, dt1))));
            fn1 = fmaf(f1.x, f1.x, fmaf(f1.y, f1.y, fmaf(f1.z, f1.z, fmaf(f1.w, f1.w, fn1))));
            cn1 = fmaf(c1.x, c1.x, fmaf(c1.y, c1.y, fmaf(c1.z, c1.z, fmaf(c1.w, c1.w, cn1))));
        }
        #pragma unroll
        for (int off = 16; off > 0; off >>= 1) {
            dt0 += __shfl_xor_sync(0xffffffffu, dt0, off);
            fn0 += __shfl_xor_sync(0xffffffffu, fn0, off);
            cn0 += __shfl_xor_sync(0xffffffffu, cn0, off);
            dt1 += __shfl_xor_sync(0xffffffffu, dt1, off);
            fn1 += __shfl_xor_sync(0xffffffffu, fn1, off);
            cn1 += __shfl_xor_sync(0xffffffffu, cn1, off);
        }

        __shared__ float sh[8];
        if (lane == 0) {
            float d0 = fmaxf(sqrtf(fn0), 1e-8f) * fmaxf(sqrtf(cn0), 1e-8f);
            float d1 = fmaxf(sqrtf(fn1), 1e-8f) * fmaxf(sqrtf(cn1), 1e-8f);
            out[1 + r0] = dt0 / d0;
            out[1 + r1] = dt1 / d1;
            // sum of squared diffs: ||f||^2 - 2 f.c + ||c||^2  (both rows)
            sh[warp] = (fn0 - 2.f * dt0 + cn0) + (fn1 - 2.f * dt1 + cn1);
        }
        __syncthreads();
        if (threadIdx.x == 0) {
            float t = 0.f;
            #pragma unroll
            for (int w = 0; w < 8; w++) t += sh[w];
            g_partials[blockIdx.x] = t;
        }
    } else {
        // ---- anchor stats: one block per v ----
        // pair_sum = C * sum_c ||a_c||^2 - ||sum_c a_c||^2 (pd diagonal is 0)
        const int v = blockIdx.x - MAIN_BLOCKS;
        const int t = threadIdx.x;          // 0..255, covers d and d+256
        const float* a = anchor + (size_t)v * NC * ND;

        float m0 = 0.f, m1 = 0.f, s = 0.f;
        #pragma unroll 4
        for (int c = 0; c < NC; c++) {
            float x0 = a[(size_t)c * ND + t];
            float x1 = a[(size_t)c * ND + t + 256];
            m0 += x0; m1 += x1;
            s = fmaf(x0, x0, fmaf(x1, x1, s));
        }
        float q = fmaf(m0, m0, m1 * m1);

        __shared__ float shs[256], shq[256];
        shs[t] = s; shq[t] = q;
        __syncthreads();
        #pragma unroll
        for (int off = 128; off > 0; off >>= 1) {
            if (t < off) { shs[t] += shs[t + off]; shq[t] += shq[t + off]; }
            __syncthreads();
        }
        if (t == 0) {
            float S = shs[0];          // sum_c ||a_c||^2
            float M2 = shq[0];         // ||sum_c a_c||^2
            float inter = (NC * S - M2) / (float)(NC * (NC - 1));
            g_inter[v] = fmaxf(MARGIN_F - inter, 0.0f);
        }
    }
}

__global__ void __launch_bounds__(256) anchor_loss_finalize(float* __restrict__ out)
{
    const int t = threadIdx.x;  // 256 threads; 2048 partials as 512 float4
    const float4* p4 = reinterpret_cast<const float4*>(g_partials);
    float4 a = p4[t];                 // v=0 : float4 [0,256)
    float4 b = p4[t + 256];           // v=1 : float4 [256,512)
    float t0 = (a.x + a.y) + (a.z + a.w);
    float t1 = (b.x + b.y) + (b.z + b.w);

    __shared__ float s0[256], s1[256];
    s0[t] = t0; s1[t] = t1;
    __syncthreads();
    #pragma unroll
    for (int off = 128; off > 0; off >>= 1) {
        if (t < off) { s0[t] += s0[t + off]; s1[t] += s1[t + off]; }
        __syncthreads();
    }
    if (t == 0) {
        float center_mean = (s0[0] + s1[0]) / (2.0f * (float)NV * (float)NB);
        float inter_mean  = (g_inter[0] + g_inter[1]) / (float)NV;
        out[0] = center_mean + inter_mean;
    }
}

extern "C" void kernel_launch(void* const* d_in, const int* in_sizes, int n_in,
                              void* d_out, int out_size)
{
    const float* feat   = (const float*)d_in[0];
    const int*   label  = (const int*)d_in[1];
    const float* anchor = (const float*)d_in[2];
    float* out = (float*)d_out;

    anchor_loss_main<<<MAIN_BLOCKS + NV, 256>>>(feat, label, anchor, out);
    anchor_loss_finalize<<<1, 256>>>(out);
}